// round 17
// baseline (speedup 1.0000x reference)
#include <cuda_runtime.h>
#include <math.h>

#define B 64
#define C 256
#define HW 64
#define L 21
#define PITCH 66      // EVEN: float2 row accesses stay 8B-aligned

// [f][l][c][b] window-average values, fp32, bit-matching reference f4
__device__ float g_f4[2 * L * C * B];
__device__ double g_kl[L];

// ---------------------------------------------------------------------------
// 16-element pieces of the associative_scan tree (bit-identical to jax).
// ---------------------------------------------------------------------------
__device__ __forceinline__ void upsweep16(float (&a)[16])
{
    #pragma unroll
    for (int d = 0; d < 4; ++d) {
        #pragma unroll
        for (int i = 0; i < (16 >> (d + 1)); ++i) {
            int hi = (i << (d + 1)) + (1 << (d + 1)) - 1;
            int lo = (i << (d + 1)) + (1 << d) - 1;
            a[hi] = __fadd_rn(a[lo], a[hi]);
        }
    }
}

// completes scan16 (no incoming prefix)
__device__ __forceinline__ void downsweep16(float (&a)[16])
{
    #pragma unroll
    for (int d = 2; d >= 0; --d) {
        #pragma unroll
        for (int i = 1; i < (16 >> (d + 1)); ++i) {
            int m = (i << (d + 1)) + (1 << d) - 1;
            a[m] = __fadd_rn(a[(i << (d + 1)) - 1], a[m]);
        }
    }
}

// down-sweep of a 16-quarter inside the 64-scan, given carry cl = tree value
// of the element just before this quarter. Caller must set u[15] (the
// quarter's top node) BEFORE calling. First mid of each level takes prefix
// cl; the rest take internal values. u[15] is never a prefix source.
__device__ __forceinline__ void downsweep16_carry(float (&u)[16], float cl)
{
    #pragma unroll
    for (int d = 3; d >= 0; --d) {
        #pragma unroll
        for (int i = 0; i < (16 >> (d + 1)); ++i) {
            int m = (i << (d + 1)) + (1 << d) - 1;
            float pre = (i == 0) ? cl : u[(i << (d + 1)) - 1];
            u[m] = __fadd_rn(pre, u[m]);
        }
    }
}

// ---------------------------------------------------------------------------
// Kernel A: one (f, b, channel) per 256-thread block. t = tid&63 = column
// (phase 1) / row (phase 2); q = tid>>6 = which 16-quarter of the 64-deep
// scan this thread owns. Quarter carries cross via smem:
//   cl1=T0, X1=fadd(T0,T1), cl2=X1, cl3=fadd(X1,T2)
//   tops: pos31=fadd(T0,T1), pos47=fadd(X1,T2), pos63=fadd(X1,fadd(T2,T3))
// — node-for-node identical to the proven half-split scan64 tree.
// ---------------------------------------------------------------------------
__global__ __launch_bounds__(256) void pool_kernel(
    const float* __restrict__ f1, const float* __restrict__ f2,
    const float* __restrict__ pre1, const float* __restrict__ pre2)
{
    __shared__ __align__(16) float S1[HW][PITCH];   // full integral-image tile
    __shared__ float s_T[4][64];               // quarter totals (phase1 cols / phase2 rows)
    __shared__ int s_flag[HW];                 // rows needed by corner extraction
    __shared__ int s_left[L], s_right[L], s_down[L], s_upper[L];
    __shared__ float s_s[L];

    int bx = blockIdx.x;
    int c = bx & 255;
    int fb = bx >> 8;
    int b = fb & 63;
    int f = fb >> 6;

    const float* feat = f ? f2 : f1;
    const float* pre  = f ? pre2 : pre1;

    int tid = threadIdx.x;
    int q = tid >> 6;
    int t = tid & 63;

    // ---- phase 1: quarter-column loads (coalesced 128B per warp) ----
    const float* p = feat + ((size_t)b * C + c) * (HW * HW) + (size_t)(q * 16) * HW + t;
    float a[16];
    #pragma unroll
    for (int j = 0; j < 16; ++j) a[j] = __ldg(p + j * HW);

    if (tid < HW) s_flag[tid] = 0;
    if (tid < L) {
        float x = pre[(b * L + tid) * 2 + 0];
        float y = pre[(b * L + tid) * 2 + 1];
        int left  = (int)fmaxf(x - 6.0f, 0.0f);   // clamp then trunc (non-neg)
        int right = (int)fminf(x + 6.0f, 63.0f);
        int down  = (int)fmaxf(y - 6.0f, 0.0f);
        int upper = (int)fminf(y + 6.0f, 63.0f);
        s_left[tid] = left;  s_right[tid] = right;
        s_down[tid] = down;  s_upper[tid] = upper;
        // divisor uses INCLUSIVE window (faithful quirk)
        s_s[tid] = (float)((upper - down + 1) * (right - left + 1));
    }

    upsweep16(a);                               // a[15] = T_q
    s_T[q][t] = a[15];
    __syncthreads();                            // T's, flags-zero, landmarks visible

    // mark rows needed for corners (benign same-value races)
    if (tid < L) {
        s_flag[s_right[tid] - 1] = 1;           // right >= 6
        if (s_left[tid] > 0) s_flag[s_left[tid] - 1] = 1;
    }

    {
        float T0 = s_T[0][t], T1 = s_T[1][t], T2 = s_T[2][t];
        float X1 = __fadd_rn(T0, T1);
        if (q == 0) {
            downsweep16(a);
        } else if (q == 1) {
            a[15] = __fadd_rn(T0, a[15]);       // pos31
            downsweep16_carry(a, T0);
        } else if (q == 2) {
            a[15] = __fadd_rn(X1, a[15]);       // pos47
            downsweep16_carry(a, X1);
        } else {
            float cl = __fadd_rn(X1, T2);
            a[15] = __fadd_rn(X1, __fadd_rn(T2, a[15]));   // pos63 (tree order!)
            downsweep16_carry(a, cl);
        }
    }
    #pragma unroll
    for (int j = 0; j < 16; ++j) S1[q * 16 + j][t] = a[j];
    __syncthreads();

    // ---- phase 2: row t (if needed), quarter q along w ----
    int act = s_flag[t];
    if (act) {
        #pragma unroll
        for (int k = 0; k < 8; ++k) {
            float2 v = *(const float2*)&S1[t][q * 16 + 2 * k];
            a[2 * k] = v.x; a[2 * k + 1] = v.y;
        }
        upsweep16(a);
        s_T[q][t] = a[15];                      // row quarter totals (safe: old reads done)
    }
    __syncthreads();
    if (act) {
        float U0 = s_T[0][t], U1 = s_T[1][t], U2 = s_T[2][t];
        float Y1 = __fadd_rn(U0, U1);
        if (q == 0) {
            downsweep16(a);
        } else if (q == 1) {
            a[15] = __fadd_rn(U0, a[15]);
            downsweep16_carry(a, U0);
        } else if (q == 2) {
            a[15] = __fadd_rn(Y1, a[15]);
            downsweep16_carry(a, Y1);
        } else {
            float cl = __fadd_rn(Y1, U2);
            a[15] = __fadd_rn(Y1, __fadd_rn(U2, a[15]));
            downsweep16_carry(a, cl);
        }
        #pragma unroll
        for (int k = 0; k < 8; ++k) {
            float2 v; v.x = a[2 * k]; v.y = a[2 * k + 1];
            *(float2*)&S1[t][q * 16 + 2 * k] = v;   // thread-exclusive segment
        }
    }
    __syncthreads();

    // ---- corners: padded P[i][j] = (i>0 && j>0) ? P2[i-1][j-1] : 0 ----
    if (tid < L) {
        int l = tid;
        int left = s_left[l], right = s_right[l];
        int down = s_down[l], upper = s_upper[l];
        float Pru = S1[right - 1][upper - 1];   // right,upper >= 6
        float Prd = (down > 0) ? S1[right - 1][down - 1] : 0.0f;
        float Plu = 0.0f, Pld = 0.0f;
        if (left > 0) {
            Plu = S1[left - 1][upper - 1];
            if (down > 0) Pld = S1[left - 1][down - 1];
        }
        // jax eval order: ((Pru - Plu) - Prd) + Pld, fp32
        float rect = __fadd_rn(__fsub_rn(__fsub_rn(Pru, Plu), Prd), Pld);
        float f4 = rect / s_s[l];               // IEEE fp32 div
        g_f4[(((size_t)f * L + l) * C + c) * B + b] = f4;
    }
}

// ---------------------------------------------------------------------------
// Kernel B: fp32 sequential batch mean + EMA (emulating XLA), fp64 downstream.
// One block per landmark, 256 threads = channels. [f][l][c][b] layout gives
// each thread 64 contiguous floats; interleaved dual chains, full unroll.
// Add order ascending b (bit-exact).
// ---------------------------------------------------------------------------
__global__ __launch_bounds__(256) void kl_kernel(
    const float* __restrict__ fea1, const float* __restrict__ fea2)
{
    int l = blockIdx.x;
    int c = threadIdx.x;

    const float4* q1 = (const float4*)&g_f4[(((size_t)0 * L + l) * C + c) * B];
    const float4* q2 = (const float4*)&g_f4[(((size_t)1 * L + l) * C + c) * B];

    float s1 = 0.0f, s2 = 0.0f;
    #pragma unroll
    for (int k = 0; k < 16; ++k) {               // ascending b, sequential
        float4 v1 = __ldg(q1 + k);
        float4 v2 = __ldg(q2 + k);
        s1 = __fadd_rn(s1, v1.x); s1 = __fadd_rn(s1, v1.y);
        s1 = __fadd_rn(s1, v1.z); s1 = __fadd_rn(s1, v1.w);
        s2 = __fadd_rn(s2, v2.x); s2 = __fadd_rn(s2, v2.y);
        s2 = __fadd_rn(s2, v2.z); s2 = __fadd_rn(s2, v2.w);
    }
    float m1 = __fdiv_rn(s1, 64.0f);             // exact (pow2)
    float m2 = __fdiv_rn(s2, 64.0f);

    const float MM = 0.999f;
    const float OM = (float)(1.0 - 0.999);
    float fc1f = __fadd_rn(__fmul_rn(MM, m1), __fmul_rn(OM, fea1[l * C + c]));
    float fc2f = __fadd_rn(__fmul_rn(MM, m2), __fmul_rn(OM, fea2[l * C + c]));

    // ---- fp64 downstream (truth; ref's fp32 downstream error ~1e-4 rel) ----
    double fc1 = (double)fc1f, fc2 = (double)fc2f;

    __shared__ double sh[8];
    int warp = c >> 5, lane = c & 31;

    // block-max fc1
    double m = fc1;
    #pragma unroll
    for (int o = 16; o > 0; o >>= 1) {
        double tt = __shfl_xor_sync(0xffffffffu, m, o);
        m = fmax(m, tt);
    }
    if (lane == 0) sh[warp] = m;
    __syncthreads();
    m = sh[lane & 7];
    #pragma unroll
    for (int o = 4; o > 0; o >>= 1) {
        double tt = __shfl_xor_sync(0xffffffffu, m, o);
        m = fmax(m, tt);
    }

    // block-sum exp(fc1 - m)
    double se = exp(fc1 - m);
    #pragma unroll
    for (int o = 16; o > 0; o >>= 1) se += __shfl_xor_sync(0xffffffffu, se, o);
    __syncthreads();
    if (lane == 0) sh[warp] = se;
    __syncthreads();
    se = sh[lane & 7];
    #pragma unroll
    for (int o = 4; o > 0; o >>= 1) se += __shfl_xor_sync(0xffffffffu, se, o);

    double log_p = (fc1 - m) - log(se);

    // block-sum fc2
    double S2 = fc2;
    #pragma unroll
    for (int o = 16; o > 0; o >>= 1) S2 += __shfl_xor_sync(0xffffffffu, S2, o);
    __syncthreads();
    if (lane == 0) sh[warp] = S2;
    __syncthreads();
    S2 = sh[lane & 7];
    #pragma unroll
    for (int o = 4; o > 0; o >>= 1) S2 += __shfl_xor_sync(0xffffffffu, S2, o);

    double qq = fc2 / S2;
    double term = (qq > 0.0) ? qq * (log(qq) - log_p) : 0.0;

    // block-sum KL terms
    double kl = term;
    #pragma unroll
    for (int o = 16; o > 0; o >>= 1) kl += __shfl_xor_sync(0xffffffffu, kl, o);
    __syncthreads();
    if (lane == 0) sh[warp] = kl;
    __syncthreads();
    if (c == 0) {
        double tt = 0.0;
        #pragma unroll
        for (int w = 0; w < 8; ++w) tt += sh[w];
        g_kl[l] = tt;
    }
}

// ---------------------------------------------------------------------------
// Kernel C: mean over 21 landmarks -> fp32 scalar.
// ---------------------------------------------------------------------------
__global__ void final_kernel(float* __restrict__ out)
{
    int t = threadIdx.x;
    double v = (t < L) ? g_kl[t] : 0.0;
    #pragma unroll
    for (int o = 16; o > 0; o >>= 1) v += __shfl_xor_sync(0xffffffffu, v, o);
    if (t == 0) out[0] = (float)(v / 21.0);
}

extern "C" void kernel_launch(void* const* d_in, const int* in_sizes, int n_in,
                              void* d_out, int out_size)
{
    const float* f1   = (const float*)d_in[0];
    const float* f2   = (const float*)d_in[1];
    const float* pre1 = (const float*)d_in[2];
    const float* pre2 = (const float*)d_in[3];
    const float* fea1 = (const float*)d_in[4];
    const float* fea2 = (const float*)d_in[5];
    float* out = (float*)d_out;

    pool_kernel<<<2 * B * C, 256>>>(f1, f2, pre1, pre2);
    kl_kernel<<<L, 256>>>(fea1, fea2);
    final_kernel<<<1, 32>>>(out);
}